// round 11
// baseline (speedup 1.0000x reference)
#include <cuda_runtime.h>
#include <cstdint>

// x: (8, 32, 32, 32, 32) f32   -> d_in[0]
// W: (32, 16, 3, 3, 3)   f32   -> d_in[1]
// b: (16,)               f32   -> d_in[2]
// out: (8, 1, 10, 10, 10) f32  -> d_out (8000 elements)

#define NG16      500         // groups of 16 cells
#define THREADS   512
#define GRID_BLKS 152

// smem layout (floats):
//   xs : [0, +32768)                4 quads x [ci][pos][cell4] float4;
//                                   float4 index = q*2048 + ci*64 + d*16+h*4+w
//   red: [32768, +512)              per-warp cmax[32] (4 cells x 8 co-half)
//   cb : [33280, +16)               per-cell gmem base offsets (int)
//   ctr broadcast uint after cb
#define XS_OFF   0
#define RED_OFF  (XS_OFF + 32768)
#define CB_OFF   (RED_OFF + 512)
#define SMEM_FLOATS (CB_OFF + 16 + 8)
#define SMEM_BYTES  (SMEM_FLOATS * 4)

__device__ unsigned g_ctr;
__device__ float    g_wt[13824];           // staging for transposed W
__constant__ ulonglong2 cWs2[3456];        // W as [ci][k][co], 55296 B

__device__ __forceinline__ unsigned long long pack2(float v) {
    unsigned long long r;
    asm("mov.b64 %0, {%1, %1};" : "=l"(r) : "f"(v));
    return r;
}
__device__ __forceinline__ void fma2(unsigned long long& d,
                                     unsigned long long a,
                                     unsigned long long b) {
    asm("fma.rn.f32x2 %0, %1, %2, %0;" : "+l"(d) : "l"(a), "l"(b));
}
__device__ __forceinline__ void unpack2(unsigned long long v, float& lo, float& hi) {
    asm("mov.b64 {%0, %1}, %2;" : "=f"(lo), "=f"(hi) : "l"(v));
}

// W global [ci][co][k] -> g_wt [ci][k][co]
extern "C" __global__ void wt_transpose_kernel(const float* __restrict__ W)
{
    int i = blockIdx.x * blockDim.x + threadIdx.x;
    if (i < 13824) {
        int ci = i / 432;
        int r  = i - ci * 432;
        int k  = r / 16;
        int co = r - k * 16;
        g_wt[i] = W[ci * 432 + co * 27 + k];
    }
}

extern "C" __global__ void __launch_bounds__(THREADS, 1)
fused_ct3d_pool_kernel(const float* __restrict__ x,
                       const float* __restrict__ b,
                       float* __restrict__ out)
{
    extern __shared__ float smem[];
    float4* xs4 = reinterpret_cast<float4*>(smem + XS_OFF);
    float*  red = smem + RED_OFF;
    int*    cb  = (int*)(smem + CB_OFF);
    unsigned* ctr_bc = (unsigned*)(smem + CB_OFF + 16);

    const int tid = threadIdx.x;

    float bsum = 0.f;
    #pragma unroll
    for (int i = 0; i < 16; i++) bsum += b[i];

    const int warp = tid >> 5;       // 0..15
    const int lane = tid & 31;
    const int quad = warp >> 2;      // 0..3 : cell-quad within group of 16
    const int role = (warp >> 1) & 1;// 0 = {7,3,1} (14 units), 1 = {6,5,4,2,0} (13)
    const int half = warp & 1;       // co-half: co 8*half .. 8*half+7

    // lane -> position within a 3x3x3 parity class (lanes 27..31 dup q=26)
    const int q  = (lane < 27) ? lane : 26;
    const int a  = q / 9;
    const int bq = (q - a * 9) / 3;
    const int c  = q - a * 9 - bq * 3;

    const float4* xq = xs4 + quad * 2048;

    // staging decomposition of tid
    const int s_ci = tid >> 4;
    const int s_d  = (tid >> 2) & 3;
    const int s_h  = tid & 3;

    while (true) {
        __syncthreads();            // previous iteration fully consumed
        if (tid == 0) *ctr_bc = atomicAdd(&g_ctr, 1u);
        __syncthreads();
        const unsigned g = *ctr_bc;
        if (g >= NG16) break;

        // ---- per-cell gmem base offsets ----
        if (tid < 16) {
            const int cell = g * 16 + tid;
            const int n  = cell / 1000;
            const int r3 = cell - n * 1000;
            const int pz = r3 / 100;
            const int py = (r3 / 10) % 10;
            const int px = r3 % 10;
            cb[tid] = n * 32 * 32768 + 3 * pz * 1024 + 3 * py * 32 + 3 * px;
        }
        __syncthreads();

        // ---- Stage 4 quads; thread handles (ci, d, h) for all 4 cells of a quad ----
        #pragma unroll 1
        for (int qq = 0; qq < 4; qq++) {
            float v[4][4];
            #pragma unroll
            for (int cc = 0; cc < 4; cc++) {
                const float* src = x + cb[qq * 4 + cc] + s_ci * 32768 + s_d * 1024 + s_h * 32;
                v[cc][0] = src[0]; v[cc][1] = src[1]; v[cc][2] = src[2]; v[cc][3] = src[3];
            }
            float4* dst = xs4 + qq * 2048 + s_ci * 64 + s_d * 16 + s_h * 4;
            #pragma unroll
            for (int w = 0; w < 4; w++) {
                float4 o;
                o.x = v[0][w]; o.y = v[1][w]; o.z = v[2][w]; o.w = v[3][w];
                dst[w] = o;
            }
        }
        __syncthreads();

        // ---- Compute: warp = (quad, role, half); 4 cells, 8 co ----
        float cmax[4][8];
        #pragma unroll
        for (int cc = 0; cc < 4; cc++)
            #pragma unroll
            for (int i = 0; i < 8; i++) cmax[cc][i] = -3.402823466e38f;

        const int ncls = role ? 5 : 3;
        #pragma unroll 1
        for (int ic = 0; ic < ncls; ic++) {
            int cls;
            if (role) { const int lb[5] = {6, 5, 4, 2, 0}; cls = lb[ic]; }
            else      { const int la[3] = {7, 3, 1};       cls = la[ic]; }
            const int pd = (cls >> 2) & 1;
            const int ph = (cls >> 1) & 1;
            const int pw = cls & 1;

            unsigned long long acc[4][4];
            #pragma unroll
            for (int cc = 0; cc < 4; cc++)
                #pragma unroll
                for (int i = 0; i < 4; i++) acc[cc][i] = 0ull;

            const int nd = pd + 1, nh = ph + 1, nw = pw + 1;
            #pragma unroll 1
            for (int td = 0; td < nd; td++) {
                const int kd = pd ? (2 * td)     : 1;
                const int rd = pd ? (a + 1 - td) : a;
                #pragma unroll 1
                for (int th2 = 0; th2 < nh; th2++) {
                    const int kh = ph ? (2 * th2)      : 1;
                    const int rh = ph ? (bq + 1 - th2) : bq;
                    #pragma unroll 1
                    for (int tw2 = 0; tw2 < nw; tw2++) {
                        const int kw = pw ? (2 * tw2)   : 1;
                        const int rw = pw ? (c + 1 - tw2) : c;
                        const int k  = (kd * 3 + kh) * 3 + kw;
                        const int xoff = rd * 16 + rh * 4 + rw;
                        const float4* xp = xq + xoff;
                        // constant-memory weights: uniform address -> LDCU port
                        const ulonglong2* wp = cWs2 + k * 4 + half * 2;
                        #pragma unroll 4
                        for (int ci = 0; ci < 32; ci++) {
                            float4 xv = xp[ci * 64];
                            unsigned long long xx0 = pack2(xv.x);
                            unsigned long long xx1 = pack2(xv.y);
                            unsigned long long xx2 = pack2(xv.z);
                            unsigned long long xx3 = pack2(xv.w);
                            ulonglong2 wA = wp[ci * 108 + 0];
                            ulonglong2 wB = wp[ci * 108 + 1];
                            fma2(acc[0][0], xx0, wA.x); fma2(acc[0][1], xx0, wA.y);
                            fma2(acc[0][2], xx0, wB.x); fma2(acc[0][3], xx0, wB.y);
                            fma2(acc[1][0], xx1, wA.x); fma2(acc[1][1], xx1, wA.y);
                            fma2(acc[1][2], xx1, wB.x); fma2(acc[1][3], xx1, wB.y);
                            fma2(acc[2][0], xx2, wA.x); fma2(acc[2][1], xx2, wA.y);
                            fma2(acc[2][2], xx2, wB.x); fma2(acc[2][3], xx2, wB.y);
                            fma2(acc[3][0], xx3, wA.x); fma2(acc[3][1], xx3, wA.y);
                            fma2(acc[3][2], xx3, wB.x); fma2(acc[3][3], xx3, wB.y);
                        }
                    }
                }
            }
            #pragma unroll
            for (int cc = 0; cc < 4; cc++)
                #pragma unroll
                for (int i = 0; i < 4; i++) {
                    float lo, hi;
                    unpack2(acc[cc][i], lo, hi);
                    cmax[cc][2 * i]     = fmaxf(cmax[cc][2 * i], lo);
                    cmax[cc][2 * i + 1] = fmaxf(cmax[cc][2 * i + 1], hi);
                }
        }

        // ---- per-warp butterfly max over positions ----
        #pragma unroll
        for (int cc = 0; cc < 4; cc++)
            #pragma unroll
            for (int i = 0; i < 8; i++) {
                #pragma unroll
                for (int off = 16; off; off >>= 1)
                    cmax[cc][i] = fmaxf(cmax[cc][i],
                                        __shfl_xor_sync(0xffffffffu, cmax[cc][i], off));
            }
        if (lane == 0) {
            #pragma unroll
            for (int cc = 0; cc < 4; cc++)
                #pragma unroll
                for (int i = 0; i < 8; i++)
                    red[warp * 32 + cc * 8 + i] = cmax[cc][i];
        }
        __syncthreads();

        // ---- combine roles per (cell, co), sum over co, write out ----
        if (tid < 16) {
            const int qd = tid >> 2;      // quad
            const int cc = tid & 3;       // cell within quad
            float t = 0.f;
            #pragma unroll
            for (int hf = 0; hf < 2; hf++)
                #pragma unroll
                for (int i = 0; i < 8; i++) {
                    const float vA = red[(qd * 4 + 0 * 2 + hf) * 32 + cc * 8 + i];
                    const float vB = red[(qd * 4 + 1 * 2 + hf) * 32 + cc * 8 + i];
                    t += fmaxf(vA, vB);
                }
            out[g * 16 + tid] = t + bsum;
        }
    }
}

extern "C" void kernel_launch(void* const* d_in, const int* in_sizes, int n_in,
                              void* d_out, int out_size)
{
    const float* x = (const float*)d_in[0];
    const float* W = (const float*)d_in[1];
    const float* b = (const float*)d_in[2];
    float* out = (float*)d_out;

    // reset work-stealing counter
    void* ctr_addr = nullptr;
    cudaGetSymbolAddress(&ctr_addr, g_ctr);
    cudaMemsetAsync(ctr_addr, 0, sizeof(unsigned));

    // transpose W into staging, then copy into __constant__
    wt_transpose_kernel<<<54, 256>>>(W);
    void* wt_addr = nullptr;
    cudaGetSymbolAddress(&wt_addr, g_wt);
    cudaMemcpyToSymbolAsync(cWs2, wt_addr, 13824 * sizeof(float), 0,
                            cudaMemcpyDeviceToDevice);

    cudaFuncSetAttribute(fused_ct3d_pool_kernel,
                         cudaFuncAttributeMaxDynamicSharedMemorySize, SMEM_BYTES);
    fused_ct3d_pool_kernel<<<GRID_BLKS, THREADS, SMEM_BYTES>>>(x, b, out);
}

// round 12
// speedup vs baseline: 1.0066x; 1.0066x over previous
#include <cuda_runtime.h>
#include <cstdint>

// x: (8, 32, 32, 32, 32) f32   -> d_in[0]
// W: (32, 16, 3, 3, 3)   f32   -> d_in[1]
// b: (16,)               f32   -> d_in[2]
// out: (8, 1, 10, 10, 10) f32  -> d_out (8000 elements)

#define NG16      500         // groups of 16 cells
#define THREADS   512
#define GRID_BLKS 152

// smem layout (floats):
//   Ws : [0, 13824)                 W as [ci][k][co]  (ci*432 + k*16 + co)
//   xs : [13824, +32768)            4 quads x [ci][pos][cell4] float4
//   red: [46592, +512)              per-warp cmax[32]
//   cb : [47104, +16)               per-cell gmem base offsets (int)
//   ctr broadcast uint after cb
#define WS_OFF   0
#define XS_OFF   13824
#define RED_OFF  (XS_OFF + 32768)
#define CB_OFF   (RED_OFF + 512)
#define SMEM_FLOATS (CB_OFF + 16 + 8)
#define SMEM_BYTES  (SMEM_FLOATS * 4)

__device__ unsigned g_ctr;
__device__ float    g_wt[13824];           // staging for transposed W
__constant__ ulonglong2 cWs2[3456];        // W as [ci][k][co], 55296 B

__device__ __forceinline__ unsigned long long pack2(float v) {
    unsigned long long r;
    asm("mov.b64 %0, {%1, %1};" : "=l"(r) : "f"(v));
    return r;
}
__device__ __forceinline__ void fma2(unsigned long long& d,
                                     unsigned long long a,
                                     unsigned long long b) {
    asm("fma.rn.f32x2 %0, %1, %2, %0;" : "+l"(d) : "l"(a), "l"(b));
}
__device__ __forceinline__ void unpack2(unsigned long long v, float& lo, float& hi) {
    asm("mov.b64 {%0, %1}, %2;" : "=f"(lo), "=f"(hi) : "l"(v));
}

// W global [ci][co][k] -> g_wt [ci][k][co]
extern "C" __global__ void wt_transpose_kernel(const float* __restrict__ W)
{
    int i = blockIdx.x * blockDim.x + threadIdx.x;
    if (i < 13824) {
        int ci = i / 432;
        int r  = i - ci * 432;
        int k  = r / 16;
        int co = r - k * 16;
        g_wt[i] = W[ci * 432 + co * 27 + k];
    }
}

extern "C" __global__ void __launch_bounds__(THREADS, 1)
fused_ct3d_pool_kernel(const float* __restrict__ x,
                       const float* __restrict__ W,
                       const float* __restrict__ b,
                       float* __restrict__ out)
{
    extern __shared__ float smem[];
    float*  Ws  = smem + WS_OFF;
    float4* xs4 = reinterpret_cast<float4*>(smem + XS_OFF);
    float*  red = smem + RED_OFF;
    int*    cb  = (int*)(smem + CB_OFF);
    unsigned* ctr_bc = (unsigned*)(smem + CB_OFF + 16);

    const int tid = threadIdx.x;

    // ---- Stage W once per block: global [ci][co][k] -> smem [ci][k][co] ----
    for (int i = tid; i < 13824; i += THREADS) {
        int ci = i / 432;
        int r  = i - ci * 432;
        int co = r / 27;
        int k  = r - co * 27;
        Ws[ci * 432 + k * 16 + co] = W[i];
    }
    float bsum = 0.f;
    #pragma unroll
    for (int i = 0; i < 16; i++) bsum += b[i];

    const int warp = tid >> 5;       // 0..15
    const int lane = tid & 31;
    const int quad = warp >> 2;      // 0..3 : cell-quad within group of 16
    const int role = (warp >> 1) & 1;// 0 = {7,3,1} (14 units), 1 = {6,5,4,2,0} (13)
    const int half = warp & 1;       // co-half: co 8*half .. 8*half+7

    // lane -> position within a 3x3x3 parity class (lanes 27..31 dup q=26)
    const int q  = (lane < 27) ? lane : 26;
    const int a  = q / 9;
    const int bq = (q - a * 9) / 3;
    const int c  = q - a * 9 - bq * 3;

    const float4* xq = xs4 + quad * 2048;

    // staging decomposition of tid
    const int s_ci = tid >> 4;
    const int s_d  = (tid >> 2) & 3;
    const int s_h  = tid & 3;

    while (true) {
        __syncthreads();            // previous iteration fully consumed
        if (tid == 0) *ctr_bc = atomicAdd(&g_ctr, 1u);
        __syncthreads();
        const unsigned g = *ctr_bc;
        if (g >= NG16) break;

        // ---- per-cell gmem base offsets ----
        if (tid < 16) {
            const int cell = g * 16 + tid;
            const int n  = cell / 1000;
            const int r3 = cell - n * 1000;
            const int pz = r3 / 100;
            const int py = (r3 / 10) % 10;
            const int px = r3 % 10;
            cb[tid] = n * 32 * 32768 + 3 * pz * 1024 + 3 * py * 32 + 3 * px;
        }
        __syncthreads();

        // ---- Stage 4 quads; thread handles (ci, d, h) for all 4 cells of a quad ----
        #pragma unroll 1
        for (int qq = 0; qq < 4; qq++) {
            float v[4][4];
            #pragma unroll
            for (int cc = 0; cc < 4; cc++) {
                const float* src = x + cb[qq * 4 + cc] + s_ci * 32768 + s_d * 1024 + s_h * 32;
                v[cc][0] = src[0]; v[cc][1] = src[1]; v[cc][2] = src[2]; v[cc][3] = src[3];
            }
            float4* dst = xs4 + qq * 2048 + s_ci * 64 + s_d * 16 + s_h * 4;
            #pragma unroll
            for (int w = 0; w < 4; w++) {
                float4 o;
                o.x = v[0][w]; o.y = v[1][w]; o.z = v[2][w]; o.w = v[3][w];
                dst[w] = o;
            }
        }
        __syncthreads();

        // ---- Compute: warp = (quad, role, half); 4 cells, 8 co ----
        float cmax[4][8];
        #pragma unroll
        for (int cc = 0; cc < 4; cc++)
            #pragma unroll
            for (int i = 0; i < 8; i++) cmax[cc][i] = -3.402823466e38f;

        const int ncls = role ? 5 : 3;
        #pragma unroll 1
        for (int ic = 0; ic < ncls; ic++) {
            int cls;
            if (role) { const int lb[5] = {6, 5, 4, 2, 0}; cls = lb[ic]; }
            else      { const int la[3] = {7, 3, 1};       cls = la[ic]; }
            const int pd = (cls >> 2) & 1;
            const int ph = (cls >> 1) & 1;
            const int pw = cls & 1;

            unsigned long long acc[4][4];
            #pragma unroll
            for (int cc = 0; cc < 4; cc++)
                #pragma unroll
                for (int i = 0; i < 4; i++) acc[cc][i] = 0ull;

            const int nd = pd + 1, nh = ph + 1, nw = pw + 1;
            #pragma unroll 1
            for (int td = 0; td < nd; td++) {
                const int kd = pd ? (2 * td)     : 1;
                const int rd = pd ? (a + 1 - td) : a;
                #pragma unroll 1
                for (int th2 = 0; th2 < nh; th2++) {
                    const int kh = ph ? (2 * th2)      : 1;
                    const int rh = ph ? (bq + 1 - th2) : bq;
                    #pragma unroll 1
                    for (int tw2 = 0; tw2 < nw; tw2++) {
                        const int kw = pw ? (2 * tw2)   : 1;
                        const int rw = pw ? (c + 1 - tw2) : c;
                        const int k  = (kd * 3 + kh) * 3 + kw;
                        const int xoff = rd * 16 + rh * 4 + rw;
                        const float4* xp = xq + xoff;
                        // hybrid weight fetch: wA via shared (L1 crossbar),
                        // wB via __constant__ (LDC port) — split the streams.
                        const ulonglong2* wps =
                            reinterpret_cast<const ulonglong2*>(Ws) + k * 4 + half * 2;
                        const ulonglong2* wpc = cWs2 + k * 4 + half * 2 + 1;
                        #pragma unroll 4
                        for (int ci = 0; ci < 32; ci++) {
                            float4 xv = xp[ci * 64];
                            unsigned long long xx0 = pack2(xv.x);
                            unsigned long long xx1 = pack2(xv.y);
                            unsigned long long xx2 = pack2(xv.z);
                            unsigned long long xx3 = pack2(xv.w);
                            ulonglong2 wA = wps[ci * 108];      // smem
                            ulonglong2 wB = wpc[ci * 108];      // const
                            fma2(acc[0][0], xx0, wA.x); fma2(acc[0][1], xx0, wA.y);
                            fma2(acc[0][2], xx0, wB.x); fma2(acc[0][3], xx0, wB.y);
                            fma2(acc[1][0], xx1, wA.x); fma2(acc[1][1], xx1, wA.y);
                            fma2(acc[1][2], xx1, wB.x); fma2(acc[1][3], xx1, wB.y);
                            fma2(acc[2][0], xx2, wA.x); fma2(acc[2][1], xx2, wA.y);
                            fma2(acc[2][2], xx2, wB.x); fma2(acc[2][3], xx2, wB.y);
                            fma2(acc[3][0], xx3, wA.x); fma2(acc[3][1], xx3, wA.y);
                            fma2(acc[3][2], xx3, wB.x); fma2(acc[3][3], xx3, wB.y);
                        }
                    }
                }
            }
            #pragma unroll
            for (int cc = 0; cc < 4; cc++)
                #pragma unroll
                for (int i = 0; i < 4; i++) {
                    float lo, hi;
                    unpack2(acc[cc][i], lo, hi);
                    cmax[cc][2 * i]     = fmaxf(cmax[cc][2 * i], lo);
                    cmax[cc][2 * i + 1] = fmaxf(cmax[cc][2 * i + 1], hi);
                }
        }

        // ---- per-warp butterfly max over positions ----
        #pragma unroll
        for (int cc = 0; cc < 4; cc++)
            #pragma unroll
            for (int i = 0; i < 8; i++) {
                #pragma unroll
                for (int off = 16; off; off >>= 1)
                    cmax[cc][i] = fmaxf(cmax[cc][i],
                                        __shfl_xor_sync(0xffffffffu, cmax[cc][i], off));
            }
        if (lane == 0) {
            #pragma unroll
            for (int cc = 0; cc < 4; cc++)
                #pragma unroll
                for (int i = 0; i < 8; i++)
                    red[warp * 32 + cc * 8 + i] = cmax[cc][i];
        }
        __syncthreads();

        // ---- combine roles per (cell, co), sum over co, write out ----
        if (tid < 16) {
            const int qd = tid >> 2;      // quad
            const int cc = tid & 3;       // cell within quad
            float t = 0.f;
            #pragma unroll
            for (int hf = 0; hf < 2; hf++)
                #pragma unroll
                for (int i = 0; i < 8; i++) {
                    const float vA = red[(qd * 4 + 0 * 2 + hf) * 32 + cc * 8 + i];
                    const float vB = red[(qd * 4 + 1 * 2 + hf) * 32 + cc * 8 + i];
                    t += fmaxf(vA, vB);
                }
            out[g * 16 + tid] = t + bsum;
        }
    }
}

extern "C" void kernel_launch(void* const* d_in, const int* in_sizes, int n_in,
                              void* d_out, int out_size)
{
    const float* x = (const float*)d_in[0];
    const float* W = (const float*)d_in[1];
    const float* b = (const float*)d_in[2];
    float* out = (float*)d_out;

    // reset work-stealing counter
    void* ctr_addr = nullptr;
    cudaGetSymbolAddress(&ctr_addr, g_ctr);
    cudaMemsetAsync(ctr_addr, 0, sizeof(unsigned));

    // transpose W into staging, then copy into __constant__
    wt_transpose_kernel<<<54, 256>>>(W);
    void* wt_addr = nullptr;
    cudaGetSymbolAddress(&wt_addr, g_wt);
    cudaMemcpyToSymbolAsync(cWs2, wt_addr, 13824 * sizeof(float), 0,
                            cudaMemcpyDeviceToDevice);

    cudaFuncSetAttribute(fused_ct3d_pool_kernel,
                         cudaFuncAttributeMaxDynamicSharedMemorySize, SMEM_BYTES);
    fused_ct3d_pool_kernel<<<GRID_BLKS, THREADS, SMEM_BYTES>>>(x, W, b, out);
}

// round 13
// speedup vs baseline: 1.0773x; 1.0702x over previous
#include <cuda_runtime.h>
#include <cstdint>

// x: (8, 32, 32, 32, 32) f32   -> d_in[0]
// W: (32, 16, 3, 3, 3)   f32   -> d_in[1]
// b: (16,)               f32   -> d_in[2]
// out: (8, 1, 10, 10, 10) f32  -> d_out (8000 elements)

#define NG16      500         // groups of 16 cells
#define THREADS   512
#define GRID_BLKS 152

// smem layout (floats):
//   Ws : [0, 13824)                 W as [ci][k][co]  (ci*432 + k*16 + co)
//   xs : [13824, +32768)            4 quads x [ci][slot][cell4] float4;
//                                   slot = bank-balanced permutation of (d,h,w)
//   red: [46592, +512)              per-warp cmax[32]
//   cb : [47104, +16)               per-cell gmem base offsets (int)
//   ctr broadcast uint after cb
#define WS_OFF   0
#define XS_OFF   13824
#define RED_OFF  (XS_OFF + 32768)
#define CB_OFF   (RED_OFF + 512)
#define SMEM_FLOATS (CB_OFF + 16 + 8)
#define SMEM_BYTES  (SMEM_FLOATS * 4)

__device__ unsigned g_ctr;

__device__ __forceinline__ unsigned long long pack2(float v) {
    unsigned long long r;
    asm("mov.b64 %0, {%1, %1};" : "=l"(r) : "f"(v));
    return r;
}
__device__ __forceinline__ void fma2(unsigned long long& d,
                                     unsigned long long a,
                                     unsigned long long b) {
    asm("fma.rn.f32x2 %0, %1, %2, %0;" : "+l"(d) : "l"(a), "l"(b));
}
__device__ __forceinline__ void unpack2(unsigned long long v, float& lo, float& hi) {
    asm("mov.b64 {%0, %1}, %2;" : "=f"(lo), "=f"(hi) : "l"(v));
}

// Bank-balanced slot permutation for the 4x4x4 x-window.
// 16B-line class k = (d + 2h + 5w) mod 8: every 3x3x3 sub-cube hits each
// class with multiplicity <= 4 (LDS.128 wavefront floor), and the full 4^3
// cube has exactly 8 members per class -> injective slot = k + 8*(2w+rank).
__device__ __forceinline__ int xslot(int d, int h, int w) {
    int k  = (d + 2 * h + 5 * w) & 7;
    int r2 = (k >= 2) ? (h & 1) : (d >> 1);
    return k + 8 * ((w << 1) + r2);
}

extern "C" __global__ void __launch_bounds__(THREADS, 1)
fused_ct3d_pool_kernel(const float* __restrict__ x,
                       const float* __restrict__ W,
                       const float* __restrict__ b,
                       float* __restrict__ out)
{
    extern __shared__ float smem[];
    float*  Ws  = smem + WS_OFF;
    float4* xs4 = reinterpret_cast<float4*>(smem + XS_OFF);
    float*  red = smem + RED_OFF;
    int*    cb  = (int*)(smem + CB_OFF);
    unsigned* ctr_bc = (unsigned*)(smem + CB_OFF + 16);

    const int tid = threadIdx.x;

    // ---- Stage W once per block: global [ci][co][k] -> smem [ci][k][co] ----
    for (int i = tid; i < 13824; i += THREADS) {
        int ci = i / 432;
        int r  = i - ci * 432;
        int co = r / 27;
        int k  = r - co * 27;
        Ws[ci * 432 + k * 16 + co] = W[i];
    }
    float bsum = 0.f;
    #pragma unroll
    for (int i = 0; i < 16; i++) bsum += b[i];

    const int warp = tid >> 5;       // 0..15
    const int lane = tid & 31;
    const int quad = warp >> 2;      // 0..3 : cell-quad within group of 16
    const int role = (warp >> 1) & 1;// 0 = {7,3,1} (14 units), 1 = {6,5,4,2,0} (13)
    const int half = warp & 1;       // co-half: co 8*half .. 8*half+7

    // lane -> position within a 3x3x3 parity class (lanes 27..31 dup q=26)
    const int q  = (lane < 27) ? lane : 26;
    const int a  = q / 9;
    const int bq = (q - a * 9) / 3;
    const int c  = q - a * 9 - bq * 3;

    const float4* xq = xs4 + quad * 2048;

    // staging decomposition of tid
    const int s_ci = tid >> 4;
    const int s_d  = (tid >> 2) & 3;
    const int s_h  = tid & 3;

    while (true) {
        __syncthreads();            // previous iteration fully consumed
        if (tid == 0) *ctr_bc = atomicAdd(&g_ctr, 1u);
        __syncthreads();
        const unsigned g = *ctr_bc;
        if (g >= NG16) break;

        // ---- per-cell gmem base offsets ----
        if (tid < 16) {
            const int cell = g * 16 + tid;
            const int n  = cell / 1000;
            const int r3 = cell - n * 1000;
            const int pz = r3 / 100;
            const int py = (r3 / 10) % 10;
            const int px = r3 % 10;
            cb[tid] = n * 32 * 32768 + 3 * pz * 1024 + 3 * py * 32 + 3 * px;
        }
        __syncthreads();

        // ---- Stage 4 quads; thread handles (ci, d, h) for all 4 cells of a quad ----
        #pragma unroll 1
        for (int qq = 0; qq < 4; qq++) {
            float v[4][4];
            #pragma unroll
            for (int cc = 0; cc < 4; cc++) {
                const float* src = x + cb[qq * 4 + cc] + s_ci * 32768 + s_d * 1024 + s_h * 32;
                v[cc][0] = src[0]; v[cc][1] = src[1]; v[cc][2] = src[2]; v[cc][3] = src[3];
            }
            float4* dst = xs4 + qq * 2048 + s_ci * 64;
            #pragma unroll
            for (int w = 0; w < 4; w++) {
                float4 o;
                o.x = v[0][w]; o.y = v[1][w]; o.z = v[2][w]; o.w = v[3][w];
                dst[xslot(s_d, s_h, w)] = o;
            }
        }
        __syncthreads();

        // ---- Compute: warp = (quad, role, half); 4 cells, 8 co ----
        float cmax[4][8];
        #pragma unroll
        for (int cc = 0; cc < 4; cc++)
            #pragma unroll
            for (int i = 0; i < 8; i++) cmax[cc][i] = -3.402823466e38f;

        const int ncls = role ? 5 : 3;
        #pragma unroll 1
        for (int ic = 0; ic < ncls; ic++) {
            int cls;
            if (role) { const int lb[5] = {6, 5, 4, 2, 0}; cls = lb[ic]; }
            else      { const int la[3] = {7, 3, 1};       cls = la[ic]; }
            const int pd = (cls >> 2) & 1;
            const int ph = (cls >> 1) & 1;
            const int pw = cls & 1;

            unsigned long long acc[4][4];
            #pragma unroll
            for (int cc = 0; cc < 4; cc++)
                #pragma unroll
                for (int i = 0; i < 4; i++) acc[cc][i] = 0ull;

            const int nd = pd + 1, nh = ph + 1, nw = pw + 1;
            #pragma unroll 1
            for (int td = 0; td < nd; td++) {
                const int kd = pd ? (2 * td)     : 1;
                const int rd = pd ? (a + 1 - td) : a;
                #pragma unroll 1
                for (int th2 = 0; th2 < nh; th2++) {
                    const int kh = ph ? (2 * th2)      : 1;
                    const int rh = ph ? (bq + 1 - th2) : bq;
                    #pragma unroll 1
                    for (int tw2 = 0; tw2 < nw; tw2++) {
                        const int kw = pw ? (2 * tw2)   : 1;
                        const int rw = pw ? (c + 1 - tw2) : c;
                        const int k  = (kd * 3 + kh) * 3 + kw;
                        const float4* xp = xq + xslot(rd, rh, rw);
                        const ulonglong2* wp =
                            reinterpret_cast<const ulonglong2*>(Ws) + k * 4 + half * 2;
                        #pragma unroll 4
                        for (int ci = 0; ci < 32; ci++) {
                            float4 xv = xp[ci * 64];
                            unsigned long long xx0 = pack2(xv.x);
                            unsigned long long xx1 = pack2(xv.y);
                            unsigned long long xx2 = pack2(xv.z);
                            unsigned long long xx3 = pack2(xv.w);
                            ulonglong2 wA = wp[ci * 108 + 0];
                            ulonglong2 wB = wp[ci * 108 + 1];
                            fma2(acc[0][0], xx0, wA.x); fma2(acc[0][1], xx0, wA.y);
                            fma2(acc[0][2], xx0, wB.x); fma2(acc[0][3], xx0, wB.y);
                            fma2(acc[1][0], xx1, wA.x); fma2(acc[1][1], xx1, wA.y);
                            fma2(acc[1][2], xx1, wB.x); fma2(acc[1][3], xx1, wB.y);
                            fma2(acc[2][0], xx2, wA.x); fma2(acc[2][1], xx2, wA.y);
                            fma2(acc[2][2], xx2, wB.x); fma2(acc[2][3], xx2, wB.y);
                            fma2(acc[3][0], xx3, wA.x); fma2(acc[3][1], xx3, wA.y);
                            fma2(acc[3][2], xx3, wB.x); fma2(acc[3][3], xx3, wB.y);
                        }
                    }
                }
            }
            #pragma unroll
            for (int cc = 0; cc < 4; cc++)
                #pragma unroll
                for (int i = 0; i < 4; i++) {
                    float lo, hi;
                    unpack2(acc[cc][i], lo, hi);
                    cmax[cc][2 * i]     = fmaxf(cmax[cc][2 * i], lo);
                    cmax[cc][2 * i + 1] = fmaxf(cmax[cc][2 * i + 1], hi);
                }
        }

        // ---- per-warp butterfly max over positions ----
        #pragma unroll
        for (int cc = 0; cc < 4; cc++)
            #pragma unroll
            for (int i = 0; i < 8; i++) {
                #pragma unroll
                for (int off = 16; off; off >>= 1)
                    cmax[cc][i] = fmaxf(cmax[cc][i],
                                        __shfl_xor_sync(0xffffffffu, cmax[cc][i], off));
            }
        if (lane == 0) {
            #pragma unroll
            for (int cc = 0; cc < 4; cc++)
                #pragma unroll
                for (int i = 0; i < 8; i++)
                    red[warp * 32 + cc * 8 + i] = cmax[cc][i];
        }
        __syncthreads();

        // ---- combine roles per (cell, co), sum over co, write out ----
        if (tid < 16) {
            const int qd = tid >> 2;      // quad
            const int cc = tid & 3;       // cell within quad
            float t = 0.f;
            #pragma unroll
            for (int hf = 0; hf < 2; hf++)
                #pragma unroll
                for (int i = 0; i < 8; i++) {
                    const float vA = red[(qd * 4 + 0 * 2 + hf) * 32 + cc * 8 + i];
                    const float vB = red[(qd * 4 + 1 * 2 + hf) * 32 + cc * 8 + i];
                    t += fmaxf(vA, vB);
                }
            out[g * 16 + tid] = t + bsum;
        }
    }
}

extern "C" void kernel_launch(void* const* d_in, const int* in_sizes, int n_in,
                              void* d_out, int out_size)
{
    const float* x = (const float*)d_in[0];
    const float* W = (const float*)d_in[1];
    const float* b = (const float*)d_in[2];
    float* out = (float*)d_out;

    // reset work-stealing counter
    void* ctr_addr = nullptr;
    cudaGetSymbolAddress(&ctr_addr, g_ctr);
    cudaMemsetAsync(ctr_addr, 0, sizeof(unsigned));

    cudaFuncSetAttribute(fused_ct3d_pool_kernel,
                         cudaFuncAttributeMaxDynamicSharedMemorySize, SMEM_BYTES);
    fused_ct3d_pool_kernel<<<GRID_BLKS, THREADS, SMEM_BYTES>>>(x, W, b, out);
}